// round 9
// baseline (speedup 1.0000x reference)
#include <cuda_runtime.h>
#include <cuda_bf16.h>
#include <cstdint>
#include <cstddef>

#define SEQ    512
#define BATCH  32
#define IND    1024
#define HID    1024
#define LAYERS 4
#define G4H    (4*HID)
#define SB     (SEQ*BATCH)       // 16384
#define SBH    ((size_t)SB*HID)  // 16777216

// ---------------- device scratch (no allocations allowed) ----------------
__device__ float g_gatesA[(size_t)SB * G4H];     // 256 MB gates ping
__device__ float g_gatesB[(size_t)SB * G4H];     // 256 MB gates pong
// W_ih for layers 1..3 pre-packed: [l-1][k][j] = ((Wi,Wf),(Wg,Wo))  (48 MB)
__device__ ulonglong2 g_wpack[3][HID][HID];
// h state pre-DUPLICATED: (h,h) u64 pairs, [k][b], double buffered (256 KB x2)
__device__ ulonglong2 g_hdup[2][HID * BATCH / 2];
__device__ __align__(128) unsigned int g_bar_count;
__device__ __align__(128) unsigned int g_bar_gen;

// ---------------- f32x2 packed-math helpers ----------------
typedef unsigned long long u64;

__device__ __forceinline__ u64 pk2(float lo, float hi) {
    u64 r; asm("mov.b64 %0, {%1, %2};" : "=l"(r) : "f"(lo), "f"(hi)); return r;
}
__device__ __forceinline__ u64 dup2(float x) {
    u64 r; asm("mov.b64 %0, {%1, %1};" : "=l"(r) : "f"(x)); return r;
}
__device__ __forceinline__ u64 ffma2(u64 a, u64 b, u64 c) {
    u64 r; asm("fma.rn.f32x2 %0, %1, %2, %3;" : "=l"(r) : "l"(a), "l"(b), "l"(c)); return r;
}
__device__ __forceinline__ u64 fadd2(u64 a, u64 b) {
    u64 r; asm("add.rn.f32x2 %0, %1, %2;" : "=l"(r) : "l"(a), "l"(b)); return r;
}
__device__ __forceinline__ float2 up2(u64 a) {
    float2 v; asm("mov.b64 {%0, %1}, %2;" : "=f"(v.x), "=f"(v.y) : "l"(a)); return v;
}

__device__ __forceinline__ float sigm(float x) { return 1.f / (1.f + expf(-x)); }
__device__ __forceinline__ float tanh_acc(float x) {
    float ax = fabsf(x);
    float e  = expf(-2.f * ax);
    float r  = (1.f - e) / (1.f + e);
    return x >= 0.f ? r : -r;
}

// ---------------- software grid barrier ----------------
// Release fence (before arrival) orders tid0's h-store path and provides the
// visibility edge; other threads' __stcg are in flight >=600cyc before any
// remote read (empirically validated R3/R8). Acquire fence dropped: all
// cross-CTA reads are __ldcg (L2-direct, no stale-L1 risk) and issue only
// after the data-dependent spin exit.
__device__ __forceinline__ void grid_barrier() {
    __syncthreads();
    if (threadIdx.x == 0) {
        __threadfence();
        volatile unsigned int* genp = &g_bar_gen;
        unsigned int old_gen = *genp;
        unsigned int arrived = atomicAdd(&g_bar_count, 1u);
        if (arrived == gridDim.x - 1) {
            g_bar_count = 0;
            __threadfence();
            atomicAdd(&g_bar_gen, 1u);
        } else {
            while (*genp == old_gen) { }
        }
    }
    __syncthreads();
}

// ================================================================
// W_ih transpose/pack (one-time, layers 1..3): wpack[l-1][k][j] holds the
// 4 gate weights of unit j at input-dim k as ((Wi,Wf),(Wg,Wo)).
// ================================================================
__global__ void pack_wih(const float* __restrict__ Wih)
{
    int l = blockIdx.z;                      // 0..2 -> layer l+1
    int k = blockIdx.y;                      // 0..1023
    int j = blockIdx.x * 256 + threadIdx.x;  // 0..1023
    const float* W = Wih + (size_t)(l + 1) * G4H * IND;
    float wi = W[(size_t)(0 * HID + j) * IND + k];
    float wf = W[(size_t)(1 * HID + j) * IND + k];
    float wg = W[(size_t)(2 * HID + j) * IND + k];
    float wo = W[(size_t)(3 * HID + j) * IND + k];
    g_wpack[l][k][j] = make_ulonglong2(pk2(wi, wf), pk2(wg, wo));
}

// ================================================================
// Layer-0 x_gates GEMM (unchanged from R8).
// ================================================================
__global__ void __launch_bounds__(256)
xgates_gemm(const float* __restrict__ A, const float* __restrict__ W,
            const float* __restrict__ bih, const float* __restrict__ bhh,
            float* __restrict__ C)
{
    __shared__ __align__(16) float As[32][128];
    __shared__ __align__(16) float Bs[32][128];

    const int tid = threadIdx.x;
    const int m0  = blockIdx.y * 128;
    const int n0  = blockIdx.x * 128;
    const int tx  = tid & 15;
    const int ty  = tid >> 4;
    const int lk  = tid & 7;
    const int lm  = tid >> 3;

    const float* Ag = A + (size_t)m0 * IND;
    const float* Wg = W + (size_t)n0 * IND;

    u64 acc[8][4];
#pragma unroll
    for (int m = 0; m < 8; m++)
#pragma unroll
        for (int p = 0; p < 4; p++) acc[m][p] = 0ull;

    for (int k0 = 0; k0 < IND; k0 += 32) {
#pragma unroll
        for (int i = 0; i < 4; i++) {
            int row = lm + i * 32;
            float4 av = *(const float4*)(Ag + (size_t)row * IND + k0 + lk * 4);
            As[lk*4+0][row] = av.x; As[lk*4+1][row] = av.y;
            As[lk*4+2][row] = av.z; As[lk*4+3][row] = av.w;
            float4 wv = *(const float4*)(Wg + (size_t)row * IND + k0 + lk * 4);
            Bs[lk*4+0][row] = wv.x; Bs[lk*4+1][row] = wv.y;
            Bs[lk*4+2][row] = wv.z; Bs[lk*4+3][row] = wv.w;
        }
        __syncthreads();
#pragma unroll
        for (int k = 0; k < 32; k++) {
            float4 a0 = *(const float4*)&As[k][ty * 8];
            float4 a1 = *(const float4*)&As[k][ty * 8 + 4];
            ulonglong2 bA = *(const ulonglong2*)&Bs[k][tx * 8];
            ulonglong2 bB = *(const ulonglong2*)&Bs[k][tx * 8 + 4];
            float am[8] = {a0.x, a0.y, a0.z, a0.w, a1.x, a1.y, a1.z, a1.w};
#pragma unroll
            for (int m = 0; m < 8; m++) {
                u64 ad = dup2(am[m]);
                acc[m][0] = ffma2(ad, bA.x, acc[m][0]);
                acc[m][1] = ffma2(ad, bA.y, acc[m][1]);
                acc[m][2] = ffma2(ad, bB.x, acc[m][2]);
                acc[m][3] = ffma2(ad, bB.y, acc[m][3]);
            }
        }
        __syncthreads();
    }

    float bias[8];
#pragma unroll
    for (int i = 0; i < 8; i++) {
        int n = n0 + tx * 8 + i;
        bias[i] = bih[n] + bhh[n];
    }
#pragma unroll
    for (int m = 0; m < 8; m++) {
        int row = m0 + ty * 8 + m;
        float2 p0 = up2(acc[m][0]);
        float2 p1 = up2(acc[m][1]);
        float2 p2 = up2(acc[m][2]);
        float2 p3 = up2(acc[m][3]);
        float4 o0 = make_float4(p0.x + bias[0], p0.y + bias[1], p1.x + bias[2], p1.y + bias[3]);
        float4 o1 = make_float4(p2.x + bias[4], p2.y + bias[5], p3.x + bias[6], p3.y + bias[7]);
        float* cp = C + (size_t)row * G4H + n0 + tx * 8;
        *(float4*)cp       = o0;
        *(float4*)(cp + 4) = o1;
    }
}

// ================================================================
// Fused persistent kernel: recurrence of layer l + x-projection of layer l+1.
// 128 CTAs x 512 threads, 1 CTA/SM. CTA owns 8 hidden units.
//  - warps 0-7  (tid<256):  recurrent GEMM h(t-1)*Whh  (v1 proven mapping,
//                           256 k per thread, pre-duplicated h loads)
//  - warps 8-15 (tid>=256): projection gates_{l+1}[it-1] = y_l[it-1]*Wih^T
//                           using the SAME hdup loads + packed Wih from L2.
//    (y_l[it-1] == h stored into hdup[it&1] at the end of iter it-1.)
// Iterations it=0..SEQ: recurrent work while it<SEQ, projection while it>0.
// fma work doubles per step but fills the latency-idle fma pipe (R8: 25%).
// smem = 128KB Whh + 2x16.9KB padded reduction = 164864 B.
// ================================================================
#define RED_STRIDE 33
#define RED_BYTES  (32 * RED_STRIDE * 16)              // 16896
#define REC_SMEM   (HID*8*16 + 2*RED_BYTES)            // 164864

__global__ void __launch_bounds__(512, 1)
lstm_fused(const float* __restrict__ gates_in,   // [512*32*4096] layer l gates
           const float* __restrict__ Whh,        // [4096*1024]  layer l
           const ulonglong2* __restrict__ wproj, // packed Wih layer l+1 ([k][j]) or null
           const float* __restrict__ bih_n,      // layer l+1 biases (valid if wproj)
           const float* __restrict__ bhh_n,
           float* __restrict__ gates_out,        // layer l+1 gates (if wproj)
           float* __restrict__ y,                // layer output (if store_y)
           int store_y,
           float* __restrict__ hlast,            // [32*1024]
           float* __restrict__ clast)            // [32*1024]
{
    extern __shared__ char smem[];
    ulonglong2* Wsm  = (ulonglong2*)smem;                          // [k*8+u]
    ulonglong2* redA = (ulonglong2*)(smem + HID * 8 * 16);
    ulonglong2* redB = (ulonglong2*)(smem + HID * 8 * 16 + RED_BYTES);

    const int tid = threadIdx.x;
    const int cta = blockIdx.x;
    const int j0  = cta * 8;

    // preload W_hh slice (coalesced along k)
    for (int i = tid; i < HID * 8; i += 512) {
        int u = i >> 10, k = i & 1023;
        int j = j0 + u;
        float wi = Whh[(size_t)(0 * HID + j) * HID + k];
        float wf = Whh[(size_t)(1 * HID + j) * HID + k];
        float wg = Whh[(size_t)(2 * HID + j) * HID + k];
        float wo = Whh[(size_t)(3 * HID + j) * HID + k];
        Wsm[k * 8 + u] = make_ulonglong2(pk2(wi, wf), pk2(wg, wo));
    }
    // zero hdup(t=0)
    {
        int idx = cta * 512 + tid;
        if (idx < HID * BATCH) ((u64*)g_hdup[0])[idx] = 0ull;
    }

    // ---- roles ----
    // recurrent GEMM (tid<256): ks 0..3 (256 k), uu unit, hb batch-quad
    const int ks = tid >> 6;
    const int rr = tid & 63;
    const int uu = rr & 7;
    const int hb = rr >> 3;
    // recurrent pointwise (tid<256)
    const int pb = tid & 31;
    const int pu = tid >> 5;
    const int pj = j0 + pu;
    // projection (tid>=256): mirror roles
    const int s   = tid & 255;
    const int ks2 = s >> 6;
    const int rr2 = s & 63;
    const int uu2 = rr2 & 7;
    const int hb2 = rr2 >> 3;
    const int pb2 = s & 31;
    const int pu2 = s >> 5;
    const int pj2 = j0 + pu2;

    // preload next-layer bias pairs (constant over t)
    u64 bIF = 0ull, bGO = 0ull;
    if (tid >= 256 && wproj) {
        bIF = pk2(bih_n[pj2]         + bhh_n[pj2],
                  bih_n[HID + pj2]   + bhh_n[HID + pj2]);
        bGO = pk2(bih_n[2*HID + pj2] + bhh_n[2*HID + pj2],
                  bih_n[3*HID + pj2] + bhh_n[3*HID + pj2]);
    }

    grid_barrier();

    float c_state = 0.f;

    for (int it = 0; it <= SEQ; it++) {
        const bool do_rec = (it < SEQ);
        const bool do_pj  = (wproj != nullptr) && (it > 0);
        const ulonglong2* hd = g_hdup[it & 1];

        float xg_i = 0.f, xg_f = 0.f, xg_g = 0.f, xg_o = 0.f;

        if (tid < 256) {
            if (do_rec) {
                // prefetch x-gates (independent of h)
                const float* gb = gates_in + ((size_t)it * BATCH + pb) * G4H + pj;
                xg_i = gb[0]; xg_f = gb[HID]; xg_g = gb[2*HID]; xg_o = gb[3*HID];

                u64 aIF0=0,aIF1=0,aIF2=0,aIF3=0,aGO0=0,aGO1=0,aGO2=0,aGO3=0;
                const int kbeg = ks << 8;
#pragma unroll 8
                for (int k = kbeg; k < kbeg + 256; k++) {
                    ulonglong2 ha = __ldcg(&hd[k * 16 + hb * 2]);
                    ulonglong2 hv = __ldcg(&hd[k * 16 + hb * 2 + 1]);
                    ulonglong2 wv = Wsm[k * 8 + uu];
                    aIF0 = ffma2(ha.x, wv.x, aIF0); aGO0 = ffma2(ha.x, wv.y, aGO0);
                    aIF1 = ffma2(ha.y, wv.x, aIF1); aGO1 = ffma2(ha.y, wv.y, aGO1);
                    aIF2 = ffma2(hv.x, wv.x, aIF2); aGO2 = ffma2(hv.x, wv.y, aGO2);
                    aIF3 = ffma2(hv.y, wv.x, aIF3); aGO3 = ffma2(hv.y, wv.y, aGO3);
                }
                ulonglong2* rp = &redA[(ks * 8 + uu) * RED_STRIDE + (hb << 2)];
                rp[0] = make_ulonglong2(aIF0, aGO0);
                rp[1] = make_ulonglong2(aIF1, aGO1);
                rp[2] = make_ulonglong2(aIF2, aGO2);
                rp[3] = make_ulonglong2(aIF3, aGO3);
            }
        } else if (do_pj) {
            u64 aIF0=0,aIF1=0,aIF2=0,aIF3=0,aGO0=0,aGO1=0,aGO2=0,aGO3=0;
            const ulonglong2* wp = wproj + (j0 + uu2);
            const int kbeg = ks2 << 8;
#pragma unroll 8
            for (int k = kbeg; k < kbeg + 256; k++) {
                ulonglong2 ha = __ldcg(&hd[k * 16 + hb2 * 2]);
                ulonglong2 hv = __ldcg(&hd[k * 16 + hb2 * 2 + 1]);
                ulonglong2 wv = __ldcg(&wp[(size_t)k * HID]);
                aIF0 = ffma2(ha.x, wv.x, aIF0); aGO0 = ffma2(ha.x, wv.y, aGO0);
                aIF1 = ffma2(ha.y, wv.x, aIF1); aGO1 = ffma2(ha.y, wv.y, aGO1);
                aIF2 = ffma2(hv.x, wv.x, aIF2); aGO2 = ffma2(hv.x, wv.y, aGO2);
                aIF3 = ffma2(hv.y, wv.x, aIF3); aGO3 = ffma2(hv.y, wv.y, aGO3);
            }
            ulonglong2* rp = &redB[(ks2 * 8 + uu2) * RED_STRIDE + (hb2 << 2)];
            rp[0] = make_ulonglong2(aIF0, aGO0);
            rp[1] = make_ulonglong2(aIF1, aGO1);
            rp[2] = make_ulonglong2(aIF2, aGO2);
            rp[3] = make_ulonglong2(aIF3, aGO3);
        }
        __syncthreads();

        if (tid < 256) {
            if (do_rec) {
                u64 sIF = pk2(xg_i, xg_f);
                u64 sGO = pk2(xg_g, xg_o);
#pragma unroll
                for (int q = 0; q < 4; q++) {
                    ulonglong2 v = redA[(q * 8 + pu) * RED_STRIDE + pb];
                    sIF = fadd2(sIF, v.x);
                    sGO = fadd2(sGO, v.y);
                }
                float2 vif = up2(sIF);
                float2 vgo = up2(sGO);
                float gi = sigm(vif.x), gf = sigm(vif.y);
                float gg = tanh_acc(vgo.x), go = sigm(vgo.y);
                float cn = gf * c_state + gi * gg;
                float hn = go * tanh_acc(cn);
                c_state = cn;

                __stcg((float2*)&((u64*)g_hdup[(it + 1) & 1])[pj * BATCH + pb],
                       make_float2(hn, hn));
                if (store_y) y[((size_t)it * BATCH + pb) * HID + pj] = hn;
                if (it == SEQ - 1) {
                    hlast[pb * HID + pj] = hn;
                    clast[pb * HID + pj] = cn;
                }
            }
        } else if (do_pj) {
            u64 sIF = bIF;
            u64 sGO = bGO;
#pragma unroll
            for (int q = 0; q < 4; q++) {
                ulonglong2 v = redB[(q * 8 + pu2) * RED_STRIDE + pb2];
                sIF = fadd2(sIF, v.x);
                sGO = fadd2(sGO, v.y);
            }
            float2 vif = up2(sIF);
            float2 vgo = up2(sGO);
            float* go_ = gates_out + ((size_t)(it - 1) * BATCH + pb2) * G4H + pj2;
            go_[0]       = vif.x;
            go_[HID]     = vif.y;
            go_[2 * HID] = vgo.x;
            go_[3 * HID] = vgo.y;
        }

        if (it < SEQ) grid_barrier();
    }
}

// ================================================================
// Host launch: pack + layer-0 GEMM + 4 fused persistent kernels.
// ================================================================
extern "C" void kernel_launch(void* const* d_in, const int* in_sizes, int n_in,
                              void* d_out, int out_size)
{
    const float* x   = (const float*)d_in[0];
    const float* Wih = (const float*)d_in[1];
    const float* Whh = (const float*)d_in[2];
    const float* bih = (const float*)d_in[3];
    const float* bhh = (const float*)d_in[4];

    float* out    = (float*)d_out;               // [512, 32, 1024]
    float* hstack = out + SBH;                   // [4, 32, 1024]
    float* cstack = hstack + (size_t)LAYERS * BATCH * HID;

    cudaFuncSetAttribute(lstm_fused, cudaFuncAttributeMaxDynamicSharedMemorySize, REC_SMEM);

    void* p;
    cudaGetSymbolAddress(&p, g_gatesA); float* gA = (float*)p;
    cudaGetSymbolAddress(&p, g_gatesB); float* gB = (float*)p;
    cudaGetSymbolAddress(&p, g_wpack);  ulonglong2* wp = (ulonglong2*)p;
    const size_t WPL = (size_t)HID * HID;   // packed elements per layer

    // one-time W_ih transpose/pack for layers 1..3
    pack_wih<<<dim3(4, 1024, 3), 256>>>(Wih);

    // layer 0 x-projection
    xgates_gemm<<<dim3(G4H / 128, SB / 128), 256>>>(
        x, Wih, bih, bhh, gA);

    float* gin[4]  = {gA, gB, gA, gB};
    float* gout[4] = {gB, gA, gB, gA};
    for (int l = 0; l < LAYERS; l++) {
        bool last = (l == LAYERS - 1);
        lstm_fused<<<128, 512, REC_SMEM>>>(
            gin[l],
            Whh + (size_t)l * G4H * HID,
            last ? nullptr : (wp + (size_t)l * WPL),
            bih + (size_t)(l + 1 < LAYERS ? l + 1 : 0) * G4H,
            bhh + (size_t)(l + 1 < LAYERS ? l + 1 : 0) * G4H,
            gout[l],
            last ? out : gA /*unused*/,
            last ? 1 : 0,
            hstack + (size_t)l * BATCH * HID,
            cstack + (size_t)l * BATCH * HID);
    }
}

// round 14
// speedup vs baseline: 2.6584x; 2.6584x over previous
#include <cuda_runtime.h>
#include <cuda_bf16.h>
#include <cstdint>
#include <cstddef>

#define SEQ    512
#define BATCH  32
#define IND    1024
#define HID    1024
#define LAYERS 4
#define G4H    (4*HID)
#define SB     (SEQ*BATCH)       // 16384
#define SBH    ((size_t)SB*HID)  // 16777216

// ---------------- device scratch (no allocations allowed) ----------------
__device__ float g_gates[(size_t)SB * G4H];      // 256 MB: x-projection + biases
__device__ float g_ybuf[2][SBH];                 // 128 MB: layer output ping-pong
__device__ float g_h[2][HID * BATCH];            // plain h[k][b], double buffered
__device__ __align__(128) unsigned int g_bar_count;
__device__ __align__(128) unsigned int g_bar_gen;

// ---------------- f32x2 packed-math helpers ----------------
typedef unsigned long long u64;

__device__ __forceinline__ u64 pk2(float lo, float hi) {
    u64 r; asm("mov.b64 %0, {%1, %2};" : "=l"(r) : "f"(lo), "f"(hi)); return r;
}
__device__ __forceinline__ u64 dup2(float x) {
    u64 r; asm("mov.b64 %0, {%1, %1};" : "=l"(r) : "f"(x)); return r;
}
__device__ __forceinline__ u64 ffma2(u64 a, u64 b, u64 c) {
    u64 r; asm("fma.rn.f32x2 %0, %1, %2, %3;" : "=l"(r) : "l"(a), "l"(b), "l"(c)); return r;
}
__device__ __forceinline__ u64 fadd2(u64 a, u64 b) {
    u64 r; asm("add.rn.f32x2 %0, %1, %2;" : "=l"(r) : "l"(a), "l"(b)); return r;
}
__device__ __forceinline__ float2 up2(u64 a) {
    float2 v; asm("mov.b64 {%0, %1}, %2;" : "=f"(v.x), "=f"(v.y) : "l"(a)); return v;
}

__device__ __forceinline__ float sigm(float x) { return 1.f / (1.f + expf(-x)); }
__device__ __forceinline__ float tanh_acc(float x) {
    float ax = fabsf(x);
    float e  = expf(-2.f * ax);
    float r  = (1.f - e) / (1.f + e);
    return x >= 0.f ? r : -r;
}

// ---------------- software grid barrier (release-only; validated R3/R8) --
__device__ __forceinline__ void grid_barrier() {
    __syncthreads();
    if (threadIdx.x == 0) {
        __threadfence();
        volatile unsigned int* genp = &g_bar_gen;
        unsigned int old_gen = *genp;
        unsigned int arrived = atomicAdd(&g_bar_count, 1u);
        if (arrived == gridDim.x - 1) {
            g_bar_count = 0;
            __threadfence();
            atomicAdd(&g_bar_gen, 1u);
        } else {
            while (*genp == old_gen) { }
        }
    }
    __syncthreads();
}

// ================================================================
// x_gates GEMM (unchanged from R8 baseline).
// ================================================================
__global__ void __launch_bounds__(256)
xgates_gemm(const float* __restrict__ A, const float* __restrict__ W,
            const float* __restrict__ bih, const float* __restrict__ bhh,
            float* __restrict__ C)
{
    __shared__ __align__(16) float As[32][128];
    __shared__ __align__(16) float Bs[32][128];

    const int tid = threadIdx.x;
    const int m0  = blockIdx.y * 128;
    const int n0  = blockIdx.x * 128;
    const int tx  = tid & 15;
    const int ty  = tid >> 4;
    const int lk  = tid & 7;
    const int lm  = tid >> 3;

    const float* Ag = A + (size_t)m0 * IND;
    const float* Wg = W + (size_t)n0 * IND;

    u64 acc[8][4];
#pragma unroll
    for (int m = 0; m < 8; m++)
#pragma unroll
        for (int p = 0; p < 4; p++) acc[m][p] = 0ull;

    for (int k0 = 0; k0 < IND; k0 += 32) {
#pragma unroll
        for (int i = 0; i < 4; i++) {
            int row = lm + i * 32;
            float4 av = *(const float4*)(Ag + (size_t)row * IND + k0 + lk * 4);
            As[lk*4+0][row] = av.x; As[lk*4+1][row] = av.y;
            As[lk*4+2][row] = av.z; As[lk*4+3][row] = av.w;
            float4 wv = *(const float4*)(Wg + (size_t)row * IND + k0 + lk * 4);
            Bs[lk*4+0][row] = wv.x; Bs[lk*4+1][row] = wv.y;
            Bs[lk*4+2][row] = wv.z; Bs[lk*4+3][row] = wv.w;
        }
        __syncthreads();
#pragma unroll
        for (int k = 0; k < 32; k++) {
            float4 a0 = *(const float4*)&As[k][ty * 8];
            float4 a1 = *(const float4*)&As[k][ty * 8 + 4];
            ulonglong2 bA = *(const ulonglong2*)&Bs[k][tx * 8];
            ulonglong2 bB = *(const ulonglong2*)&Bs[k][tx * 8 + 4];
            float am[8] = {a0.x, a0.y, a0.z, a0.w, a1.x, a1.y, a1.z, a1.w};
#pragma unroll
            for (int m = 0; m < 8; m++) {
                u64 ad = dup2(am[m]);
                acc[m][0] = ffma2(ad, bA.x, acc[m][0]);
                acc[m][1] = ffma2(ad, bA.y, acc[m][1]);
                acc[m][2] = ffma2(ad, bB.x, acc[m][2]);
                acc[m][3] = ffma2(ad, bB.y, acc[m][3]);
            }
        }
        __syncthreads();
    }

    float bias[8];
#pragma unroll
    for (int i = 0; i < 8; i++) {
        int n = n0 + tx * 8 + i;
        bias[i] = bih[n] + bhh[n];
    }
#pragma unroll
    for (int m = 0; m < 8; m++) {
        int row = m0 + ty * 8 + m;
        float2 p0 = up2(acc[m][0]);
        float2 p1 = up2(acc[m][1]);
        float2 p2 = up2(acc[m][2]);
        float2 p3 = up2(acc[m][3]);
        float4 o0 = make_float4(p0.x + bias[0], p0.y + bias[1], p1.x + bias[2], p1.y + bias[3]);
        float4 o1 = make_float4(p2.x + bias[4], p2.y + bias[5], p3.x + bias[6], p3.y + bias[7]);
        float* cp = C + (size_t)row * G4H + n0 + tx * 8;
        *(float4*)cp       = o0;
        *(float4*)(cp + 4) = o1;
    }
}

// ================================================================
// Recurrence v3.1: explicit latency hiding + coalesced pointwise.
// 128 CTAs x 512 threads, 1 CTA/SM. CTA owns 8 hidden units.
// h is PLAIN f32 [k][b]. Inner loop double-buffers batches of 4 k so ~4-8
// LDGs/thread stay in flight regardless of ptxas batching. Outer loop not
// unrolled (16 iterations, I-cache-sized body).
// Pointwise roles pu=tid&7 (lane-fast), pb=tid>>3 — gates loads and
// y stores are 4x32B sectors/warp instead of 32.
// smem = 128KB W + 64*33*16 = 164864 B.
// ================================================================
#define RED_STRIDE 33
#define REC_SMEM (HID*8*16 + 64*RED_STRIDE*16)   // 131072 + 33792 = 164864

__global__ void __launch_bounds__(512, 1)
lstm_rec3(const float* __restrict__ gates,   // [512*32*4096]
          const float* __restrict__ Whh,     // [4096*1024]
          float* __restrict__ y,             // [512*32*1024]
          float* __restrict__ hlast,         // [32*1024]
          float* __restrict__ clast)         // [32*1024]
{
    extern __shared__ char smem[];
    ulonglong2* Wsm = (ulonglong2*)smem;                       // [k*8 + u]
    ulonglong2* red = (ulonglong2*)(smem + HID * 8 * 16);      // [(ks*8+u)*33 + b]

    const int tid = threadIdx.x;
    const int cta = blockIdx.x;
    const int j0  = cta * 8;

    // preload W_hh slice (coalesced along k)
    for (int i = tid; i < HID * 8; i += 512) {
        int u = i >> 10, k = i & 1023;
        int j = j0 + u;
        float wi = Whh[(size_t)(0 * HID + j) * HID + k];
        float wf = Whh[(size_t)(1 * HID + j) * HID + k];
        float wg = Whh[(size_t)(2 * HID + j) * HID + k];
        float wo = Whh[(size_t)(3 * HID + j) * HID + k];
        Wsm[k * 8 + u] = make_ulonglong2(pk2(wi, wf), pk2(wg, wo));
    }
    // zero h(t=0)
    {
        int idx = cta * 512 + tid;
        if (idx < HID * BATCH) g_h[0][idx] = 0.f;
    }
    grid_barrier();

    // GEMM-phase roles
    const int ks = tid >> 6;          // 0..7 (K slice of 128)
    const int uu = tid & 7;           // 0..7 (unit)
    const int hb = (tid >> 3) & 7;    // 0..7 (batch quad)
    // pointwise roles (tid < 256): pu lane-fast for coalesced gates/y
    const int pu = tid & 7;
    const int pb = tid >> 3;          // 0..31
    const int pj = j0 + pu;

    float c_state = 0.f;

    for (int t = 0; t < SEQ; t++) {
        float xg_i = 0.f, xg_f = 0.f, xg_g = 0.f, xg_o = 0.f;
        if (tid < 256) {
            const float* gb = gates + ((size_t)t * BATCH + pb) * G4H + pj;
            xg_i = gb[0]; xg_f = gb[HID]; xg_g = gb[2*HID]; xg_o = gb[3*HID];
        }

        // ---- partial GEMM over this thread's 128-k slice ----
        const float4* hp = (const float4*)g_h[t & 1] + hb;   // hp[k*8] = h[k][hb*4..+3]
        const int kb = ks << 7;

        u64 aIF0=0,aIF1=0,aIF2=0,aIF3=0,aGO0=0,aGO1=0,aGO2=0,aGO3=0;
        float4 A0,A1,A2,A3,B0,B1,B2,B3;

        A0 = __ldcg(hp + (size_t)(kb+0)*8);
        A1 = __ldcg(hp + (size_t)(kb+1)*8);
        A2 = __ldcg(hp + (size_t)(kb+2)*8);
        A3 = __ldcg(hp + (size_t)(kb+3)*8);

#define REC_COMPUTE(kk, V0, V1, V2, V3)                                        \
        {                                                                      \
            ulonglong2 w0 = Wsm[(kk+0)*8 + uu];                                \
            ulonglong2 w1 = Wsm[(kk+1)*8 + uu];                                \
            ulonglong2 w2 = Wsm[(kk+2)*8 + uu];                                \
            ulonglong2 w3 = Wsm[(kk+3)*8 + uu];                                \
            u64 d;                                                             \
            d = dup2(V0.x); aIF0=ffma2(d,w0.x,aIF0); aGO0=ffma2(d,w0.y,aGO0);  \
            d = dup2(V0.y); aIF1=ffma2(d,w0.x,aIF1); aGO1=ffma2(d,w0.y,aGO1);  \
            d = dup2(V0.z); aIF2=ffma2(d,w0.x,aIF2); aGO2=ffma2(d,w0.y,aGO2);  \
            d = dup2(V0.w); aIF3=ffma2(d,w0.x,aIF3); aGO3=ffma2(d,w0.y,aGO3);  \
            d = dup2(V1.x); aIF0=ffma2(d,w1.x,aIF0); aGO0=ffma2(d,w1.y,aGO0);  \
            d = dup2(V1.y); aIF1=ffma2(d,w1.x,aIF1); aGO1=ffma2(d,w1.y,aGO1);  \
            d = dup2(V1.z); aIF2=ffma2(d,w1.x,aIF2); aGO2=ffma2(d,w1.y,aGO2);  \
            d = dup2(V1.w); aIF3=ffma2(d,w1.x,aIF3); aGO3=ffma2(d,w1.y,aGO3);  \
            d = dup2(V2.x); aIF0=ffma2(d,w2.x,aIF0); aGO0=ffma2(d,w2.y,aGO0);  \
            d = dup2(V2.y); aIF1=ffma2(d,w2.x,aIF1); aGO1=ffma2(d,w2.y,aGO1);  \
            d = dup2(V2.z); aIF2=ffma2(d,w2.x,aIF2); aGO2=ffma2(d,w2.y,aGO2);  \
            d = dup2(V2.w); aIF3=ffma2(d,w2.x,aIF3); aGO3=ffma2(d,w2.y,aGO3);  \
            d = dup2(V3.x); aIF0=ffma2(d,w3.x,aIF0); aGO0=ffma2(d,w3.y,aGO0);  \
            d = dup2(V3.y); aIF1=ffma2(d,w3.x,aIF1); aGO1=ffma2(d,w3.y,aGO1);  \
            d = dup2(V3.z); aIF2=ffma2(d,w3.x,aIF2); aGO2=ffma2(d,w3.y,aGO2);  \
            d = dup2(V3.w); aIF3=ffma2(d,w3.x,aIF3); aGO3=ffma2(d,w3.y,aGO3);  \
        }

#pragma unroll 1
        for (int bb = 0; bb < 16; bb++) {
            int k8 = kb + bb * 8;
            B0 = __ldcg(hp + (size_t)(k8+4)*8);
            B1 = __ldcg(hp + (size_t)(k8+5)*8);
            B2 = __ldcg(hp + (size_t)(k8+6)*8);
            B3 = __ldcg(hp + (size_t)(k8+7)*8);
            REC_COMPUTE(k8, A0, A1, A2, A3);
            if (bb < 15) {
                A0 = __ldcg(hp + (size_t)(k8+8)*8);
                A1 = __ldcg(hp + (size_t)(k8+9)*8);
                A2 = __ldcg(hp + (size_t)(k8+10)*8);
                A3 = __ldcg(hp + (size_t)(k8+11)*8);
            }
            REC_COMPUTE(k8+4, B0, B1, B2, B3);
        }
#undef REC_COMPUTE

        {
            ulonglong2* rp = &red[(ks * 8 + uu) * RED_STRIDE + (hb << 2)];
            rp[0] = make_ulonglong2(aIF0, aGO0);
            rp[1] = make_ulonglong2(aIF1, aGO1);
            rp[2] = make_ulonglong2(aIF2, aGO2);
            rp[3] = make_ulonglong2(aIF3, aGO3);
        }
        __syncthreads();

        // ---- pointwise: reduce 8 K-slices, apply LSTM cell ----
        if (tid < 256) {
            u64 sIF = pk2(xg_i, xg_f);
            u64 sGO = pk2(xg_g, xg_o);
#pragma unroll
            for (int q = 0; q < 8; q++) {
                ulonglong2 v = red[(q * 8 + pu) * RED_STRIDE + pb];
                sIF = fadd2(sIF, v.x);
                sGO = fadd2(sGO, v.y);
            }
            float2 vif = up2(sIF);
            float2 vgo = up2(sGO);
            float gi = sigm(vif.x), gf = sigm(vif.y);
            float gg = tanh_acc(vgo.x), go = sigm(vgo.y);
            float cn = gf * c_state + gi * gg;
            float hn = go * tanh_acc(cn);
            c_state = cn;

            __stcg(&g_h[(t + 1) & 1][pj * BATCH + pb], hn);
            y[((size_t)t * BATCH + pb) * HID + pj] = hn;
            if (t == SEQ - 1) {
                hlast[pb * HID + pj] = hn;
                clast[pb * HID + pj] = cn;
            }
        }
        if (t < SEQ - 1) grid_barrier();
    }
}

// ================================================================
// Host launch: 4 x (GEMM + recurrence v3.1), graph-capturable.
// ================================================================
extern "C" void kernel_launch(void* const* d_in, const int* in_sizes, int n_in,
                              void* d_out, int out_size)
{
    const float* x   = (const float*)d_in[0];
    const float* Wih = (const float*)d_in[1];
    const float* Whh = (const float*)d_in[2];
    const float* bih = (const float*)d_in[3];
    const float* bhh = (const float*)d_in[4];

    float* out    = (float*)d_out;               // [512, 32, 1024]
    float* hstack = out + SBH;                   // [4, 32, 1024]
    float* cstack = hstack + (size_t)LAYERS * BATCH * HID;

    cudaFuncSetAttribute(lstm_rec3, cudaFuncAttributeMaxDynamicSharedMemorySize, REC_SMEM);

    void* p;
    cudaGetSymbolAddress(&p, g_gates); float* gates = (float*)p;
    cudaGetSymbolAddress(&p, g_ybuf);  float* ybuf  = (float*)p;

    dim3 ggrid(G4H / 128, SB / 128);  // (32, 128)
    for (int l = 0; l < LAYERS; l++) {
        const float* A = (l == 0) ? x : ybuf + (size_t)((l - 1) & 1) * SBH;
        xgates_gemm<<<ggrid, 256>>>(A,
                                    Wih + (size_t)l * G4H * IND,
                                    bih + (size_t)l * G4H,
                                    bhh + (size_t)l * G4H,
                                    gates);
        float* yt = (l < LAYERS - 1) ? ybuf + (size_t)(l & 1) * SBH : out;
        lstm_rec3<<<128, 512, REC_SMEM>>>(gates,
                                          Whh + (size_t)l * G4H * HID,
                                          yt,
                                          hstack + (size_t)l * BATCH * HID,
                                          cstack + (size_t)l * BATCH * HID);
    }
}

// round 17
// speedup vs baseline: 3.3594x; 1.2637x over previous
#include <cuda_runtime.h>
#include <cuda_bf16.h>
#include <cstdint>
#include <cstddef>

#define SEQ    512
#define BATCH  32
#define IND    1024
#define HID    1024
#define LAYERS 4
#define G4H    (4*HID)
#define SB     (SEQ*BATCH)       // 16384
#define SBH    ((size_t)SB*HID)  // 16777216

// ---------------- device scratch (no allocations allowed) ----------------
__device__ float g_gates[(size_t)SB * G4H];      // 256 MB
__device__ float g_ybuf[2][SBH];                 // 128 MB
__device__ float g_h[2][HID * BATCH];            // plain h[k][b], double buffered
__device__ __align__(128) unsigned int g_bar_count;
__device__ __align__(128) unsigned int g_bar_gen;
// split-bf16 operands, plain row-major [.][k]
__device__ __nv_bfloat16 g_a0[(size_t)SB * IND];            // 32 MB
__device__ __nv_bfloat16 g_a1[(size_t)SB * IND];            // 32 MB
__device__ __nv_bfloat16 g_w0[(size_t)LAYERS * G4H * IND];  // 32 MB
__device__ __nv_bfloat16 g_w1[(size_t)LAYERS * G4H * IND];  // 32 MB

// ---------------- f32x2 packed-math helpers ----------------
typedef unsigned long long u64;

__device__ __forceinline__ u64 pk2(float lo, float hi) {
    u64 r; asm("mov.b64 %0, {%1, %2};" : "=l"(r) : "f"(lo), "f"(hi)); return r;
}
__device__ __forceinline__ u64 dup2(float x) {
    u64 r; asm("mov.b64 %0, {%1, %1};" : "=l"(r) : "f"(x)); return r;
}
__device__ __forceinline__ u64 ffma2(u64 a, u64 b, u64 c) {
    u64 r; asm("fma.rn.f32x2 %0, %1, %2, %3;" : "=l"(r) : "l"(a), "l"(b), "l"(c)); return r;
}
__device__ __forceinline__ u64 fadd2(u64 a, u64 b) {
    u64 r; asm("add.rn.f32x2 %0, %1, %2;" : "=l"(r) : "l"(a), "l"(b)); return r;
}
__device__ __forceinline__ float2 up2(u64 a) {
    float2 v; asm("mov.b64 {%0, %1}, %2;" : "=f"(v.x), "=f"(v.y) : "l"(a)); return v;
}

__device__ __forceinline__ float sigm(float x) { return 1.f / (1.f + expf(-x)); }
__device__ __forceinline__ float tanh_acc(float x) {
    float ax = fabsf(x);
    float e  = expf(-2.f * ax);
    float r  = (1.f - e) / (1.f + e);
    return x >= 0.f ? r : -r;
}

__device__ __forceinline__ uint32_t smem_u32(const void* p) {
    uint32_t a;
    asm("{ .reg .u64 t; cvta.to.shared.u64 t, %1; cvt.u32.u64 %0, t; }" : "=r"(a) : "l"(p));
    return a;
}

// ---------------- warp MMA helpers (baseline PTX, sm_80+: compile for compute_103) --
__device__ __forceinline__ void ldsm4(uint32_t* r, uint32_t addr) {
    asm volatile("ldmatrix.sync.aligned.m8n8.x4.shared.b16 {%0,%1,%2,%3}, [%4];"
        : "=r"(r[0]), "=r"(r[1]), "=r"(r[2]), "=r"(r[3]) : "r"(addr));
}
__device__ __forceinline__ void mma_bf16(float* d, const uint32_t* a, const uint32_t* b) {
    asm volatile(
        "mma.sync.aligned.m16n8k16.row.col.f32.bf16.bf16.f32 "
        "{%0,%1,%2,%3}, {%4,%5,%6,%7}, {%8,%9}, {%0,%1,%2,%3};"
        : "+f"(d[0]), "+f"(d[1]), "+f"(d[2]), "+f"(d[3])
        : "r"(a[0]), "r"(a[1]), "r"(a[2]), "r"(a[3]), "r"(b[0]), "r"(b[1]));
}

// ---------------- software grid barrier (release-only; validated) --------
__device__ __forceinline__ void grid_barrier() {
    __syncthreads();
    if (threadIdx.x == 0) {
        __threadfence();
        volatile unsigned int* genp = &g_bar_gen;
        unsigned int old_gen = *genp;
        unsigned int arrived = atomicAdd(&g_bar_count, 1u);
        if (arrived == gridDim.x - 1) {
            g_bar_count = 0;
            __threadfence();
            atomicAdd(&g_bar_gen, 1u);
        } else {
            while (*genp == old_gen) { }
        }
    }
    __syncthreads();
}

// ================================================================
// Pack kernels: fp32 -> (bf16 hi, bf16 residual), plain row-major.
// ================================================================
__global__ void pack_w(const float* __restrict__ Wih)
{
    int l = blockIdx.z;
    int n = blockIdx.y;
    int k = blockIdx.x * 256 + threadIdx.x;
    size_t idx = ((size_t)l * G4H + n) * IND + k;
    float v = Wih[idx];
    __nv_bfloat16 hi = __float2bfloat16(v);
    g_w0[idx] = hi;
    g_w1[idx] = __float2bfloat16(v - __bfloat162float(hi));
}

__global__ void pack_a(const float* __restrict__ A)
{
    int m = blockIdx.y;
    int k = blockIdx.x * 256 + threadIdx.x;
    size_t idx = (size_t)m * IND + k;
    float v = A[idx];
    __nv_bfloat16 hi = __float2bfloat16(v);
    g_a0[idx] = hi;
    g_a1[idx] = __float2bfloat16(v - __bfloat162float(hi));
}

// ================================================================
// mma_gemm: C[16384,4096] = A x W^T + bias via warp-level bf16 MMA
// (m16n8k16, baseline PTX -> HMMA). Split-bf16 3-term:
//   C = A0W0 + A0W1 + A1W0   (A1W1 ~ 2^-16, dropped)
// CTA: 256 thr = 8 warps in 2(M)x4(N); CTA tile 128x128; warp tile 64x32
// (4x4 atoms). K-chunks of 64 (4 k-steps). smem row stride 72 bf16 (144B):
// conflict-free for STS.128 fills and all ldmatrix phases (r*144 mod 128
// distinct over 8 rows).
// ================================================================
#define SAS 72
#define TILE_B (128 * SAS * 2)                 // 18432 B per tile
#define MG_SMEM (4 * TILE_B + 512)             // 74240 B

__global__ void __launch_bounds__(256)
mma_gemm(const __nv_bfloat16* __restrict__ a0, const __nv_bfloat16* __restrict__ a1,
         const __nv_bfloat16* __restrict__ w0, const __nv_bfloat16* __restrict__ w1,
         const float* __restrict__ bih, const float* __restrict__ bhh,
         float* __restrict__ C)
{
    extern __shared__ char sm[];
    __nv_bfloat16* sA0 = (__nv_bfloat16*)sm;
    __nv_bfloat16* sA1 = (__nv_bfloat16*)(sm + TILE_B);
    __nv_bfloat16* sW0 = (__nv_bfloat16*)(sm + 2 * TILE_B);
    __nv_bfloat16* sW1 = (__nv_bfloat16*)(sm + 3 * TILE_B);
    float* sbias       = (float*)(sm + 4 * TILE_B);

    const int tid  = threadIdx.x;
    const int wid  = tid >> 5;
    const int lane = tid & 31;
    const int nt   = blockIdx.x;
    const int mt   = blockIdx.y;
    const int wm   = wid >> 2;    // 0..1
    const int wn   = wid & 3;     // 0..3

    if (tid < 128) sbias[tid] = bih[nt * 128 + tid] + bhh[nt * 128 + tid];

    // fill mapping: 2 threads per row, 64B each
    const int frow = tid >> 1;
    const int fpart = tid & 1;
    const __nv_bfloat16* ga0 = a0 + ((size_t)(mt * 128 + frow)) * IND + fpart * 32;
    const __nv_bfloat16* ga1 = a1 + ((size_t)(mt * 128 + frow)) * IND + fpart * 32;
    const __nv_bfloat16* gw0 = w0 + ((size_t)(nt * 128 + frow)) * IND + fpart * 32;
    const __nv_bfloat16* gw1 = w1 + ((size_t)(nt * 128 + frow)) * IND + fpart * 32;
    const int sdst = frow * SAS + fpart * 32;   // bf16 units

    // per-thread ldmatrix invariant offsets (bytes)
    const uint32_t smb = smem_u32(sm);
    const uint32_t aoff = (uint32_t)(((wm * 64 + (lane & 15)) * SAS + ((lane >> 4) * 8)) * 2);
    const uint32_t boff = (uint32_t)(((wn * 32 + ((lane >> 4) & 1) * 8 + (lane & 7)) * SAS
                                      + ((lane >> 3) & 1) * 8) * 2);

    float acc[4][4][4];
#pragma unroll
    for (int i = 0; i < 4; i++)
#pragma unroll
        for (int j = 0; j < 4; j++)
#pragma unroll
            for (int r = 0; r < 4; r++) acc[i][j][r] = 0.f;

    for (int c = 0; c < 16; c++) {
        const int kg = c * 64;
        {
            const uint4* s0 = (const uint4*)(ga0 + kg);
            const uint4* s1 = (const uint4*)(ga1 + kg);
            const uint4* s2 = (const uint4*)(gw0 + kg);
            const uint4* s3 = (const uint4*)(gw1 + kg);
            uint4* d0 = (uint4*)(sA0 + sdst);
            uint4* d1 = (uint4*)(sA1 + sdst);
            uint4* d2 = (uint4*)(sW0 + sdst);
            uint4* d3 = (uint4*)(sW1 + sdst);
#pragma unroll
            for (int q = 0; q < 4; q++) d0[q] = s0[q];
#pragma unroll
            for (int q = 0; q < 4; q++) d1[q] = s1[q];
#pragma unroll
            for (int q = 0; q < 4; q++) d2[q] = s2[q];
#pragma unroll
            for (int q = 0; q < 4; q++) d3[q] = s3[q];
        }
        __syncthreads();

#pragma unroll
        for (int ks = 0; ks < 4; ks++) {
            const uint32_t kso = (uint32_t)(ks * 16 * 2);
            uint32_t fa0[4][4], fa1[4][4], fb0[4][2], fb1[4][2];
#pragma unroll
            for (int i = 0; i < 4; i++) {
                uint32_t o = aoff + (uint32_t)(i * 16 * SAS * 2) + kso;
                ldsm4(fa0[i], smb + o);
                ldsm4(fa1[i], smb + (uint32_t)TILE_B + o);
            }
#pragma unroll
            for (int p = 0; p < 2; p++) {
                uint32_t o = boff + (uint32_t)(p * 16 * SAS * 2) + kso;
                uint32_t t[4];
                ldsm4(t, smb + (uint32_t)(2 * TILE_B) + o);
                fb0[2*p][0] = t[0]; fb0[2*p][1] = t[1];
                fb0[2*p+1][0] = t[2]; fb0[2*p+1][1] = t[3];
                ldsm4(t, smb + (uint32_t)(3 * TILE_B) + o);
                fb1[2*p][0] = t[0]; fb1[2*p][1] = t[1];
                fb1[2*p+1][0] = t[2]; fb1[2*p+1][1] = t[3];
            }
#pragma unroll
            for (int i = 0; i < 4; i++)
#pragma unroll
                for (int j = 0; j < 4; j++) {
                    mma_bf16(acc[i][j], fa0[i], fb0[j]);
                    mma_bf16(acc[i][j], fa0[i], fb1[j]);
                    mma_bf16(acc[i][j], fa1[i], fb0[j]);
                }
        }
        __syncthreads();
    }

    // epilogue
    const int er = lane >> 2;
    const int ec = (lane & 3) * 2;
#pragma unroll
    for (int i = 0; i < 4; i++) {
        size_t m = (size_t)(mt * 128 + wm * 64 + i * 16 + er);
#pragma unroll
        for (int j = 0; j < 4; j++) {
            int nl = wn * 32 + j * 8 + ec;
            int n = nt * 128 + nl;
            float b0v = sbias[nl], b1v = sbias[nl + 1];
            float* p0 = C + m * G4H + n;
            p0[0] = acc[i][j][0] + b0v;
            p0[1] = acc[i][j][1] + b1v;
            float* p1 = C + (m + 8) * G4H + n;
            p1[0] = acc[i][j][2] + b0v;
            p1[1] = acc[i][j][3] + b1v;
        }
    }
}

// ================================================================
// Recurrence v3.1 (BYTE-IDENTICAL to R14 winner).
// ================================================================
#define RED_STRIDE 33
#define REC_SMEM (HID*8*16 + 64*RED_STRIDE*16)   // 164864

__global__ void __launch_bounds__(512, 1)
lstm_rec3(const float* __restrict__ gates,
          const float* __restrict__ Whh,
          float* __restrict__ y,
          float* __restrict__ hlast,
          float* __restrict__ clast)
{
    extern __shared__ char smem[];
    ulonglong2* Wsm = (ulonglong2*)smem;
    ulonglong2* red = (ulonglong2*)(smem + HID * 8 * 16);

    const int tid = threadIdx.x;
    const int cta = blockIdx.x;
    const int j0  = cta * 8;

    for (int i = tid; i < HID * 8; i += 512) {
        int u = i >> 10, k = i & 1023;
        int j = j0 + u;
        float wi = Whh[(size_t)(0 * HID + j) * HID + k];
        float wf = Whh[(size_t)(1 * HID + j) * HID + k];
        float wg = Whh[(size_t)(2 * HID + j) * HID + k];
        float wo = Whh[(size_t)(3 * HID + j) * HID + k];
        Wsm[k * 8 + u] = make_ulonglong2(pk2(wi, wf), pk2(wg, wo));
    }
    {
        int idx = cta * 512 + tid;
        if (idx < HID * BATCH) g_h[0][idx] = 0.f;
    }
    grid_barrier();

    const int ks = tid >> 6;
    const int uu = tid & 7;
    const int hb = (tid >> 3) & 7;
    const int pu = tid & 7;
    const int pb = tid >> 3;
    const int pj = j0 + pu;

    float c_state = 0.f;

    for (int t = 0; t < SEQ; t++) {
        float xg_i = 0.f, xg_f = 0.f, xg_g = 0.f, xg_o = 0.f;
        if (tid < 256) {
            const float* gb = gates + ((size_t)t * BATCH + pb) * G4H + pj;
            xg_i = gb[0]; xg_f = gb[HID]; xg_g = gb[2*HID]; xg_o = gb[3*HID];
        }

        const float4* hp = (const float4*)g_h[t & 1] + hb;
        const int kb = ks << 7;

        u64 aIF0=0,aIF1=0,aIF2=0,aIF3=0,aGO0=0,aGO1=0,aGO2=0,aGO3=0;
        float4 A0,A1,A2,A3,B0,B1,B2,B3;

        A0 = __ldcg(hp + (size_t)(kb+0)*8);
        A1 = __ldcg(hp + (size_t)(kb+1)*8);
        A2 = __ldcg(hp + (size_t)(kb+2)*8);
        A3 = __ldcg(hp + (size_t)(kb+3)*8);

#define REC_COMPUTE(kk, V0, V1, V2, V3)                                        \
        {                                                                      \
            ulonglong2 w0v = Wsm[(kk+0)*8 + uu];                               \
            ulonglong2 w1v = Wsm[(kk+1)*8 + uu];                               \
            ulonglong2 w2v = Wsm[(kk+2)*8 + uu];                               \
            ulonglong2 w3v = Wsm[(kk+3)*8 + uu];                               \
            u64 d;                                                             \
            d = dup2(V0.x); aIF0=ffma2(d,w0v.x,aIF0); aGO0=ffma2(d,w0v.y,aGO0);\
            d = dup2(V0.y); aIF1=ffma2(d,w0v.x,aIF1); aGO1=ffma2(d,w0v.y,aGO1);\
            d = dup2(V0.z); aIF2=ffma2(d,w0v.x,aIF2); aGO2=ffma2(d,w0v.y,aGO2);\
            d = dup2(V0.w); aIF3=ffma2(d,w0v.x,aIF3); aGO3=ffma2(d,w0v.y,aGO3);\
            d = dup2(V1.x); aIF0=ffma2(d,w1v.x,aIF0); aGO0=ffma2(d,w1v.y,aGO0);\
            d = dup2(V1.y); aIF1=ffma2(d,w1v.x,aIF1); aGO1=ffma2(d,w1v.y,aGO1);\
            d = dup2(V1.z); aIF2=ffma2(d,w1v.x,aIF2); aGO2=ffma2(d,w1v.y,aGO2);\
            d = dup2(V1.w); aIF3=ffma2(d,w1v.x,aIF3); aGO3=ffma2(d,w1v.y,aGO3);\
            d = dup2(V2.x); aIF0=ffma2(d,w2v.x,aIF0); aGO0=ffma2(d,w2v.y,aGO0);\
            d = dup2(V2.y); aIF1=ffma2(d,w2v.x,aIF1); aGO1=ffma2(d,w2v.y,aGO1);\
            d = dup2(V2.z); aIF2=ffma2(d,w2v.x,aIF2); aGO2=ffma2(d,w2v.y,aGO2);\
            d = dup2(V2.w); aIF3=ffma2(d,w2v.x,aIF3); aGO3=ffma2(d,w2v.y,aGO3);\
            d = dup2(V3.x); aIF0=ffma2(d,w3v.x,aIF0); aGO0=ffma2(d,w3v.y,aGO0);\
            d = dup2(V3.y); aIF1=ffma2(d,w3v.x,aIF1); aGO1=ffma2(d,w3v.y,aGO1);\
            d = dup2(V3.z); aIF2=ffma2(d,w3v.x,aIF2); aGO2=ffma2(d,w3v.y,aGO2);\
            d = dup2(V3.w); aIF3=ffma2(d,w3v.x,aIF3); aGO3=ffma2(d,w3v.y,aGO3);\
        }

#pragma unroll 1
        for (int bb = 0; bb < 16; bb++) {
            int k8 = kb + bb * 8;
            B0 = __ldcg(hp + (size_t)(k8+4)*8);
            B1 = __ldcg(hp + (size_t)(k8+5)*8);
            B2 = __ldcg(hp + (size_t)(k8+6)*8);
            B3 = __ldcg(hp + (size_t)(k8+7)*8);
            REC_COMPUTE(k8, A0, A1, A2, A3);
            if (bb < 15) {
                A0 = __ldcg(hp + (size_t)(k8+8)*8);
                A1 = __ldcg(hp + (size_t)(k8+9)*8);
                A2 = __ldcg(hp + (size_t)(k8+10)*8);
                A3 = __ldcg(hp + (size_t)(k8+11)*8);
            }
            REC_COMPUTE(k8+4, B0, B1, B2, B3);
        }
#undef REC_COMPUTE

        {
            ulonglong2* rp = &red[(ks * 8 + uu) * RED_STRIDE + (hb << 2)];
            rp[0] = make_ulonglong2(aIF0, aGO0);
            rp[1] = make_ulonglong2(aIF1, aGO1);
            rp[2] = make_ulonglong2(aIF2, aGO2);
            rp[3] = make_ulonglong2(aIF3, aGO3);
        }
        __syncthreads();

        if (tid < 256) {
            u64 sIF = pk2(xg_i, xg_f);
            u64 sGO = pk2(xg_g, xg_o);
#pragma unroll
            for (int q = 0; q < 8; q++) {
                ulonglong2 v = red[(q * 8 + pu) * RED_STRIDE + pb];
                sIF = fadd2(sIF, v.x);
                sGO = fadd2(sGO, v.y);
            }
            float2 vif = up2(sIF);
            float2 vgo = up2(sGO);
            float gi = sigm(vif.x), gf = sigm(vif.y);
            float gg = tanh_acc(vgo.x), go = sigm(vgo.y);
            float cn = gf * c_state + gi * gg;
            float hn = go * tanh_acc(cn);
            c_state = cn;

            __stcg(&g_h[(t + 1) & 1][pj * BATCH + pb], hn);
            y[((size_t)t * BATCH + pb) * HID + pj] = hn;
            if (t == SEQ - 1) {
                hlast[pb * HID + pj] = hn;
                clast[pb * HID + pj] = cn;
            }
        }
        if (t < SEQ - 1) grid_barrier();
    }
}

// ================================================================
// Host launch: pack_w once + per layer (pack_a, mma_gemm, lstm_rec3).
// ================================================================
extern "C" void kernel_launch(void* const* d_in, const int* in_sizes, int n_in,
                              void* d_out, int out_size)
{
    const float* x   = (const float*)d_in[0];
    const float* Wih = (const float*)d_in[1];
    const float* Whh = (const float*)d_in[2];
    const float* bih = (const float*)d_in[3];
    const float* bhh = (const float*)d_in[4];

    float* out    = (float*)d_out;
    float* hstack = out + SBH;
    float* cstack = hstack + (size_t)LAYERS * BATCH * HID;

    cudaFuncSetAttribute(lstm_rec3, cudaFuncAttributeMaxDynamicSharedMemorySize, REC_SMEM);
    cudaFuncSetAttribute(mma_gemm,  cudaFuncAttributeMaxDynamicSharedMemorySize, MG_SMEM);

    void* p;
    cudaGetSymbolAddress(&p, g_gates); float* gates = (float*)p;
    cudaGetSymbolAddress(&p, g_ybuf);  float* ybuf  = (float*)p;
    cudaGetSymbolAddress(&p, g_a0);    __nv_bfloat16* a0 = (__nv_bfloat16*)p;
    cudaGetSymbolAddress(&p, g_a1);    __nv_bfloat16* a1 = (__nv_bfloat16*)p;
    cudaGetSymbolAddress(&p, g_w0);    __nv_bfloat16* w0 = (__nv_bfloat16*)p;
    cudaGetSymbolAddress(&p, g_w1);    __nv_bfloat16* w1 = (__nv_bfloat16*)p;

    pack_w<<<dim3(4, 4096, LAYERS), 256>>>(Wih);

    for (int l = 0; l < LAYERS; l++) {
        const float* A = (l == 0) ? x : ybuf + (size_t)((l - 1) & 1) * SBH;
        pack_a<<<dim3(4, 16384), 256>>>(A);
        size_t woff = (size_t)l * G4H * IND;
        mma_gemm<<<dim3(32, 128), 256, MG_SMEM>>>(a0, a1, w0 + woff, w1 + woff,
                                                  bih + (size_t)l * G4H,
                                                  bhh + (size_t)l * G4H,
                                                  gates);
        float* yt = (l < LAYERS - 1) ? ybuf + (size_t)(l & 1) * SBH : out;
        lstm_rec3<<<128, 512, REC_SMEM>>>(gates,
                                          Whh + (size_t)l * G4H * HID,
                                          yt,
                                          hstack + (size_t)l * BATCH * HID,
                                          cstack + (size_t)l * BATCH * HID);
    }
}